// round 4
// baseline (speedup 1.0000x reference)
#include <cuda_runtime.h>
#include <math.h>
#include <stdint.h>

#define NF 2177      // full node count
#define NM 2176      // minor size (NM = NF-1), 68*32
#define NMAT 8       // 4 batches x {z, target}
#define NSTEPS (NM/32)   // 68
#define ROWTILES 17      // 17 * 128 = 2176

// scratch (allocation-free contract: __device__ globals)
__device__ float g_A[NMAT][(size_t)NM * NM];          // ~151.5 MB
__device__ float g_part[NMAT][ROWTILES][NM];          // colsum partials
__device__ float g_logparts[NMAT][NSTEPS];            // per-step sum of log(pivot)
__device__ unsigned g_bar[NMAT];                      // per-matrix barrier counters

// ---------------------------------------------------------------------------
// Build off-diagonal: A[i][j] = -w(r=i+1, c=j+1)
// ---------------------------------------------------------------------------
__global__ void build_offdiag(const float* __restrict__ scores,
                              const float* __restrict__ tmask,
                              const float* __restrict__ zmask,
                              const int* __restrict__ lengths) {
    size_t idx = (size_t)blockIdx.x * blockDim.x + threadIdx.x;
    const size_t total = (size_t)NMAT * NM * NM;
    if (idx >= total) return;
    int j = (int)(idx % NM);
    size_t t = idx / NM;
    int i = (int)(t % NM);
    int m = (int)(t / NM);
    int b = m >> 1;
    const float* mask = (m & 1) ? tmask : zmask;
    int len = lengths[b];
    int r = i + 1, c = j + 1;
    float w = 0.0f;
    if (r < len && c < len) {
        size_t off = (size_t)b * NF * NF + (size_t)r * NF + c;
        float mk = mask[off];
        if (mk != 0.0f) w = expf(scores[off]) * mk;
    }
    g_A[m][(size_t)i * NM + j] = -w;
}

// ---------------------------------------------------------------------------
// Column sums (deterministic two-stage, no atomics)
// ---------------------------------------------------------------------------
__global__ void colsum_part() {
    int m = blockIdx.z;
    int j = blockIdx.x * 32 + threadIdx.x;
    int i0 = blockIdx.y * 128;
    const float* A = g_A[m];
    float s = 0.0f;
    int ibase = i0 + threadIdx.y * 16;
    #pragma unroll
    for (int rr = 0; rr < 16; rr++) {
        s += A[(size_t)(ibase + rr) * NM + j];
    }
    __shared__ float sh[8][32];
    sh[threadIdx.y][threadIdx.x] = s;
    __syncthreads();
    if (threadIdx.y == 0) {
        float tot = 0.0f;
        #pragma unroll
        for (int y = 0; y < 8; y++) tot += sh[y][threadIdx.x];
        g_part[m][blockIdx.y][j] = tot;
    }
}

__global__ void set_diag(const float* __restrict__ scores,
                         const float* __restrict__ tmask,
                         const float* __restrict__ zmask,
                         const int* __restrict__ lengths) {
    // reset persistent-kernel barriers (runs before it in stream order)
    if (blockIdx.x == 0 && blockIdx.y == 0 && threadIdx.x < NMAT)
        g_bar[threadIdx.x] = 0u;

    int m = blockIdx.y;
    int j = blockIdx.x * 256 + threadIdx.x;
    if (j >= NM) return;
    float s = 0.0f;
    #pragma unroll
    for (int t = 0; t < ROWTILES; t++) s += g_part[m][t][j];
    float colsum = -s;   // partials summed -w
    int b = m >> 1;
    int len = lengths[b];
    int c = j + 1;
    const float* mask = (m & 1) ? tmask : zmask;
    float diag;
    if (c < len) {
        size_t off = (size_t)b * NF * NF + c;   // row 0 (root) entry
        float w0 = expf(scores[off]) * mask[off];
        diag = colsum + w0;
    } else {
        diag = 1.0f;    // pad identity for invalid suffix
    }
    g_A[m][(size_t)j * NM + j] = diag;
}

// ---------------------------------------------------------------------------
// Per-matrix software barrier (all G blocks of the group must arrive).
// Monotone counter; reset once per launch in set_diag.
// ---------------------------------------------------------------------------
__device__ __forceinline__ void gbar(int m, unsigned target) {
    __syncthreads();
    if (threadIdx.x == 0) {
        __threadfence();
        atomicAdd(&g_bar[m], 1u);
        while (*((volatile unsigned*)&g_bar[m]) < target) __nanosleep(64);
        __threadfence();
    }
    __syncthreads();
}

// ---------------------------------------------------------------------------
// Persistent factorization: each group of G blocks owns one matrix and walks
// all 68 panel steps (LU32 diag -> fused TRSMs -> rank-32 Schur GEMM).
// ---------------------------------------------------------------------------
__global__ void __launch_bounds__(256, 4) mtt_persistent(int G) {
    const int m = blockIdx.x / G;
    const int r = blockIdx.x % G;
    float* A = g_A[m];
    const int tid = threadIdx.x;

    __shared__ float shA[32][136];   // GEMM A-slab (128x32, transposed) / LU+TRSM diag block
    __shared__ float shB[32][68];    // GEMM B-slab (32x64) / LU scratch
    __shared__ float invd[32];

    unsigned epoch = 0;

    for (int k = 0; k < NM; k += 32) {
        const int rem = NM - k - 32;

        // ---- 1) LU of 32x32 diagonal block: group block 0, warp 0 ----
        if (r == 0 && tid < 32) {
            float (*s)[33] = (float(*)[33])&shB[0][0];
            const int t = tid;
            #pragma unroll 8
            for (int q = 0; q < 32; q++)
                s[t][q] = A[(size_t)(k + t) * NM + (k + q)];
            __syncwarp();
            for (int p = 0; p < 32; p++) {
                float piv = s[p][p];
                if (t > p) {
                    float l = s[t][p] / piv;
                    s[t][p] = l;
                    for (int q = p + 1; q < 32; q++)
                        s[t][q] -= l * s[p][q];
                }
                __syncwarp();
            }
            #pragma unroll 8
            for (int q = 0; q < 32; q++)
                A[(size_t)(k + t) * NM + (k + q)] = s[t][q];
            float lg = logf(s[t][t]);
            #pragma unroll
            for (int o = 16; o; o >>= 1) lg += __shfl_xor_sync(0xffffffffu, lg, o);
            if (t == 0) g_logparts[m][k >> 5] = lg;
        }
        gbar(m, (++epoch) * (unsigned)G);

        if (rem <= 0) continue;   // uniform across the group

        // ---- 2) fused TRSMs: one smem copy of the diag block serves both ----
        {
            float (*u)[33] = (float(*)[33])&shA[0][0];
            for (int e = tid; e < 1024; e += 256)
                u[e >> 5][e & 31] = A[(size_t)(k + (e >> 5)) * NM + (k + (e & 31))];
            __syncthreads();
            if (tid < 32) invd[tid] = 1.0f / u[tid][tid];
            __syncthreads();

            // L21 = A21 * U11^{-1}   (row per thread, strided over group)
            for (int row = k + 32 + r * 256 + tid; row < NM; row += G * 256) {
                float a[32];
                const float4* ld = (const float4*)(A + (size_t)row * NM + k);
                #pragma unroll
                for (int v = 0; v < 8; v++) {
                    float4 f = ld[v];
                    a[4*v+0]=f.x; a[4*v+1]=f.y; a[4*v+2]=f.z; a[4*v+3]=f.w;
                }
                #pragma unroll
                for (int j = 0; j < 32; j++) {
                    float x = a[j];
                    #pragma unroll
                    for (int p = 0; p < j; p++) x -= a[p] * u[p][j];
                    a[j] = x * invd[j];
                }
                float4* st = (float4*)(A + (size_t)row * NM + k);
                #pragma unroll
                for (int v = 0; v < 8; v++)
                    st[v] = make_float4(a[4*v+0], a[4*v+1], a[4*v+2], a[4*v+3]);
            }
            // U12 = L11^{-1} * A12   (column per thread, coalesced)
            for (int c = k + 32 + r * 256 + tid; c < NM; c += G * 256) {
                float x[32];
                #pragma unroll
                for (int p = 0; p < 32; p++) {
                    float v = A[(size_t)(k + p) * NM + c];
                    #pragma unroll
                    for (int q = 0; q < p; q++) v -= u[p][q] * x[q];
                    x[p] = v;
                    A[(size_t)(k + p) * NM + c] = v;
                }
            }
        }
        gbar(m, (++epoch) * (unsigned)G);

        // ---- 3) Schur GEMM: C -= L21 * U12, 128x64 tiles, 8x4 per thread ----
        {
            const int base = k + 32;
            const int tpr = (rem + 127) >> 7;
            const int tpc = (rem + 63) >> 6;
            const int T = tpr * tpc;
            for (int tix = r; tix < T; tix += G) {
                __syncthreads();
                const int row0 = base + (tix / tpc) * 128;
                const int col0 = base + (tix % tpc) * 64;
                {   // load L21 slab 128x32 -> shA[q][i]
                    int q = tid & 31, y = tid >> 5;
                    #pragma unroll
                    for (int rr = 0; rr < 16; rr++) {
                        int i = rr * 8 + y;
                        int rw = row0 + i;
                        shA[q][i] = (rw < NM) ? A[(size_t)rw * NM + k + q] : 0.0f;
                    }
                }
                {   // load U12 slab 32x64 -> shB[p][j]
                    int j = tid & 63, pb = tid >> 6;
                    #pragma unroll
                    for (int rr = 0; rr < 8; rr++) {
                        int p = pb + rr * 4;
                        int cc = col0 + j;
                        shB[p][j] = (cc < NM) ? A[(size_t)(k + p) * NM + cc] : 0.0f;
                    }
                }
                __syncthreads();

                const int tx = tid & 15, ty = tid >> 4;
                float acc[8][4] = {};
                #pragma unroll
                for (int p = 0; p < 32; p++) {
                    float4 a0 = *(const float4*)&shA[p][ty * 8];
                    float4 a1 = *(const float4*)&shA[p][ty * 8 + 4];
                    float4 bv = *(const float4*)&shB[p][tx * 4];
                    float aa[8] = {a0.x,a0.y,a0.z,a0.w,a1.x,a1.y,a1.z,a1.w};
                    float bb[4] = {bv.x,bv.y,bv.z,bv.w};
                    #pragma unroll
                    for (int ii = 0; ii < 8; ii++)
                        #pragma unroll
                        for (int jj = 0; jj < 4; jj++)
                            acc[ii][jj] += aa[ii] * bb[jj];
                }

                const int cb = col0 + tx * 4;
                #pragma unroll
                for (int ii = 0; ii < 8; ii++) {
                    int rw = row0 + ty * 8 + ii;
                    if (rw >= NM) break;
                    float* cp = A + (size_t)rw * NM + cb;
                    if (cb + 3 < NM) {
                        float4 v = *(float4*)cp;
                        v.x -= acc[ii][0]; v.y -= acc[ii][1];
                        v.z -= acc[ii][2]; v.w -= acc[ii][3];
                        *(float4*)cp = v;
                    } else {
                        #pragma unroll
                        for (int jj = 0; jj < 4; jj++)
                            if (cb + jj < NM) cp[jj] -= acc[ii][jj];
                    }
                }
            }
        }
        gbar(m, (++epoch) * (unsigned)G);
    }
}

// ---------------------------------------------------------------------------
// Finalize: mean over batch of (logdet_z - logdet_t), double accumulation
// ---------------------------------------------------------------------------
__global__ void finalize(float* out) {
    double acc = 0.0;
    for (int b = 0; b < 4; b++) {
        double z = 0.0, t = 0.0;
        for (int s = 0; s < NSTEPS; s++) {
            z += (double)g_logparts[2 * b][s];
            t += (double)g_logparts[2 * b + 1][s];
        }
        acc += (z - t);
    }
    out[0] = (float)(acc * 0.25);
}

// ---------------------------------------------------------------------------
extern "C" void kernel_launch(void* const* d_in, const int* in_sizes, int n_in,
                              void* d_out, int out_size) {
    const float* scores  = (const float*)d_in[0];
    const float* tmask   = (const float*)d_in[1];
    const float* zmask   = (const float*)d_in[2];
    const int*   lengths = (const int*)d_in[3];

    const size_t total = (size_t)NMAT * NM * NM;
    build_offdiag<<<(unsigned)((total + 255) / 256), 256>>>(scores, tmask, zmask, lengths);
    colsum_part<<<dim3(NM / 32, ROWTILES, NMAT), dim3(32, 8)>>>();
    set_diag<<<dim3((NM + 255) / 256, NMAT), 256>>>(scores, tmask, zmask, lengths);

    // size the persistent grid so every block is co-resident (deadlock-free)
    int maxb = 0, sms = 0;
    cudaOccupancyMaxActiveBlocksPerMultiprocessor(&maxb, mtt_persistent, 256, 0);
    cudaDeviceGetAttribute(&sms, cudaDevAttrMultiProcessorCount, 0);
    if (maxb < 1) maxb = 1;
    if (sms  < 1) sms  = 148;
    long cap = (long)maxb * (long)sms;
    int G = (int)(cap / NMAT);
    if (G > 74) G = 74;
    if (G < 2)  G = 2;

    mtt_persistent<<<NMAT * G, 256>>>(G);
    finalize<<<1, 1>>>((float*)d_out);
}

// round 5
// speedup vs baseline: 1.3869x; 1.3869x over previous
#include <cuda_runtime.h>
#include <math.h>
#include <stdint.h>

#define NF 2177      // full node count
#define NM 2176      // minor size (NM = NF-1) = 34*64
#define NMAT 8       // 4 batches x {z, target}
#define NB 64        // panel width
#define NSTEPS (NM/NB)   // 34
#define ROWTILES 17      // 17 * 128 = 2176

// scratch (allocation-free contract: __device__ globals)
__device__ float g_A[NMAT][(size_t)NM * NM];          // ~151.5 MB
__device__ float g_part[NMAT][ROWTILES][NM];          // colsum partials
__device__ float g_logparts[NMAT][NSTEPS];            // per-step sum of log(pivot)

// ---------------------------------------------------------------------------
// Build off-diagonal: A[i][j] = -w(r=i+1, c=j+1)
// ---------------------------------------------------------------------------
__global__ void build_offdiag(const float* __restrict__ scores,
                              const float* __restrict__ tmask,
                              const float* __restrict__ zmask,
                              const int* __restrict__ lengths) {
    size_t idx = (size_t)blockIdx.x * blockDim.x + threadIdx.x;
    const size_t total = (size_t)NMAT * NM * NM;
    if (idx >= total) return;
    int j = (int)(idx % NM);
    size_t t = idx / NM;
    int i = (int)(t % NM);
    int m = (int)(t / NM);
    int b = m >> 1;
    const float* mask = (m & 1) ? tmask : zmask;
    int len = lengths[b];
    int r = i + 1, c = j + 1;
    float w = 0.0f;
    if (r < len && c < len) {
        size_t off = (size_t)b * NF * NF + (size_t)r * NF + c;
        float mk = mask[off];
        if (mk != 0.0f) w = expf(scores[off]) * mk;
    }
    g_A[m][(size_t)i * NM + j] = -w;
}

// ---------------------------------------------------------------------------
// Column sums (deterministic two-stage, no atomics)
// ---------------------------------------------------------------------------
__global__ void colsum_part() {
    int m = blockIdx.z;
    int j = blockIdx.x * 32 + threadIdx.x;
    int i0 = blockIdx.y * 128;
    const float* A = g_A[m];
    float s = 0.0f;
    int ibase = i0 + threadIdx.y * 16;
    #pragma unroll
    for (int rr = 0; rr < 16; rr++) {
        s += A[(size_t)(ibase + rr) * NM + j];
    }
    __shared__ float sh[8][32];
    sh[threadIdx.y][threadIdx.x] = s;
    __syncthreads();
    if (threadIdx.y == 0) {
        float tot = 0.0f;
        #pragma unroll
        for (int y = 0; y < 8; y++) tot += sh[y][threadIdx.x];
        g_part[m][blockIdx.y][j] = tot;
    }
}

__global__ void set_diag(const float* __restrict__ scores,
                         const float* __restrict__ tmask,
                         const float* __restrict__ zmask,
                         const int* __restrict__ lengths) {
    int m = blockIdx.y;
    int j = blockIdx.x * 256 + threadIdx.x;
    if (j >= NM) return;
    float s = 0.0f;
    #pragma unroll
    for (int t = 0; t < ROWTILES; t++) s += g_part[m][t][j];
    float colsum = -s;   // partials summed -w
    int b = m >> 1;
    int len = lengths[b];
    int c = j + 1;
    const float* mask = (m & 1) ? tmask : zmask;
    float diag;
    if (c < len) {
        size_t off = (size_t)b * NF * NF + c;   // row 0 (root) entry
        float w0 = expf(scores[off]) * mask[off];
        diag = colsum + w0;
    } else {
        diag = 1.0f;    // pad identity for invalid suffix
    }
    g_A[m][(size_t)j * NM + j] = diag;
}

// ---------------------------------------------------------------------------
// Fused panel step: every block redundantly LU-factors the 64x64 diagonal
// block in shared memory (no pivoting: column-dd M-matrix), then either
//   role RIGHT (blockIdx.x <  nR): L21 rows  = A21 * U11^{-1}
//   role LEFT  (blockIdx.x >= nR): U12 cols  = L11^{-1} * A12
// Block (0, m) also records sum of log(pivot). The factored diagonal block
// is never written back to gmem (nothing downstream reads it).
// ---------------------------------------------------------------------------
__global__ void __launch_bounds__(256) panel64(int k, int nR) {
    const int m = blockIdx.y;
    float* A = g_A[m];
    const int tid = threadIdx.x;

    __shared__ float s[NB][NB + 1];
    __shared__ float invd[NB];
    __shared__ float lred[NB];

    // load diagonal block
    for (int e = tid; e < NB * NB; e += 256) {
        int p = e >> 6, q = e & 63;
        s[p][q] = A[(size_t)(k + p) * NM + (k + q)];
    }
    __syncthreads();

    // in-smem LU, threads 0..63 (warps 0,1), named barrier per pivot step
    if (tid < NB) {
        const int t = tid;
        for (int p = 0; p < NB; p++) {
            if (t > p) {
                float l = s[t][p] / s[p][p];
                s[t][p] = l;
                for (int q = p + 1; q < NB; q++)
                    s[t][q] -= l * s[p][q];
            }
            asm volatile("bar.sync 1, 64;" ::: "memory");
        }
        invd[t] = 1.0f / s[t][t];
        lred[t] = logf(s[t][t]);
    }
    __syncthreads();

    if (blockIdx.x == 0 && tid == 0) {
        float sum = 0.0f;
        #pragma unroll
        for (int i = 0; i < NB; i++) sum += lred[i];
        g_logparts[m][k / NB] = sum;
    }

    if (blockIdx.x < nR) {
        // ---- RIGHT: one row per thread, row slice in registers ----
        int row = k + NB + blockIdx.x * 256 + tid;
        if (row >= NM) return;
        float a[NB];
        const float4* ld = (const float4*)(A + (size_t)row * NM + k);
        #pragma unroll
        for (int v = 0; v < NB / 4; v++) {
            float4 f = ld[v];
            a[4*v+0] = f.x; a[4*v+1] = f.y; a[4*v+2] = f.z; a[4*v+3] = f.w;
        }
        #pragma unroll
        for (int j = 0; j < NB; j++) {
            float x = a[j];
            for (int p = 0; p < j; p++) x -= a[p] * s[p][j];
            a[j] = x * invd[j];
        }
        float4* st = (float4*)(A + (size_t)row * NM + k);
        #pragma unroll
        for (int v = 0; v < NB / 4; v++)
            st[v] = make_float4(a[4*v+0], a[4*v+1], a[4*v+2], a[4*v+3]);
    } else {
        // ---- LEFT: one column per thread, coalesced across threads ----
        int c = k + NB + (blockIdx.x - nR) * 256 + tid;
        if (c >= NM) return;
        float x[NB];
        #pragma unroll
        for (int p = 0; p < NB; p++) {
            float v = A[(size_t)(k + p) * NM + c];
            for (int q = 0; q < p; q++) v -= s[p][q] * x[q];
            x[p] = v;
            A[(size_t)(k + p) * NM + c] = v;
        }
    }
}

// ---------------------------------------------------------------------------
// Schur update: C[k+64.., k+64..] -= L21 * U12   (K = 64, staged as 2x32)
// 128x64 tile / block, 256 threads, 8x4 per thread
// ---------------------------------------------------------------------------
__global__ void __launch_bounds__(256) schur64(int k) {
    const int m = blockIdx.z;
    float* A = g_A[m];
    const int base = k + NB;
    const int tid = threadIdx.x;
    const int row0 = base + blockIdx.y * 128;
    const int col0 = base + blockIdx.x * 64;

    __shared__ float shA[32][132];   // shA[p][i] = L21[row0+i][kh+p]
    __shared__ float shB[32][68];    // shB[p][j] = U12[kh+p][col0+j]

    const int tx = tid & 15, ty = tid >> 4;
    float acc[8][4] = {};

    #pragma unroll
    for (int h = 0; h < 2; h++) {
        const int kh = k + h * 32;
        __syncthreads();
        {   // load L21 slab 128x32 (transposed)
            int q = tid & 31, y = tid >> 5;
            #pragma unroll
            for (int rr = 0; rr < 16; rr++) {
                int i = rr * 8 + y;
                int rw = row0 + i;
                shA[q][i] = (rw < NM) ? A[(size_t)rw * NM + kh + q] : 0.0f;
            }
        }
        {   // load U12 slab 32x64
            int j = tid & 63, pb = tid >> 6;
            #pragma unroll
            for (int rr = 0; rr < 8; rr++) {
                int p = pb + rr * 4;
                shB[p][j] = A[(size_t)(kh + p) * NM + col0 + j];
            }
        }
        __syncthreads();

        #pragma unroll 8
        for (int p = 0; p < 32; p++) {
            float4 a0 = *(const float4*)&shA[p][ty * 8];
            float4 a1 = *(const float4*)&shA[p][ty * 8 + 4];
            float4 bv = *(const float4*)&shB[p][tx * 4];
            float aa[8] = {a0.x,a0.y,a0.z,a0.w,a1.x,a1.y,a1.z,a1.w};
            float bb[4] = {bv.x,bv.y,bv.z,bv.w};
            #pragma unroll
            for (int ii = 0; ii < 8; ii++)
                #pragma unroll
                for (int jj = 0; jj < 4; jj++)
                    acc[ii][jj] += aa[ii] * bb[jj];
        }
    }

    const int cb = col0 + tx * 4;
    #pragma unroll
    for (int ii = 0; ii < 8; ii++) {
        int rw = row0 + ty * 8 + ii;
        if (rw >= NM) break;
        float* cp = A + (size_t)rw * NM + cb;
        float4 v = *(float4*)cp;
        v.x -= acc[ii][0]; v.y -= acc[ii][1];
        v.z -= acc[ii][2]; v.w -= acc[ii][3];
        *(float4*)cp = v;
    }
}

// ---------------------------------------------------------------------------
// Finalize: mean over batch of (logdet_z - logdet_t), double accumulation
// ---------------------------------------------------------------------------
__global__ void finalize(float* out) {
    double acc = 0.0;
    for (int b = 0; b < 4; b++) {
        double z = 0.0, t = 0.0;
        for (int s = 0; s < NSTEPS; s++) {
            z += (double)g_logparts[2 * b][s];
            t += (double)g_logparts[2 * b + 1][s];
        }
        acc += (z - t);
    }
    out[0] = (float)(acc * 0.25);
}

// ---------------------------------------------------------------------------
extern "C" void kernel_launch(void* const* d_in, const int* in_sizes, int n_in,
                              void* d_out, int out_size) {
    const float* scores  = (const float*)d_in[0];
    const float* tmask   = (const float*)d_in[1];
    const float* zmask   = (const float*)d_in[2];
    const int*   lengths = (const int*)d_in[3];

    const size_t total = (size_t)NMAT * NM * NM;
    build_offdiag<<<(unsigned)((total + 255) / 256), 256>>>(scores, tmask, zmask, lengths);
    colsum_part<<<dim3(NM / 32, ROWTILES, NMAT), dim3(32, 8)>>>();
    set_diag<<<dim3((NM + 255) / 256, NMAT), 256>>>(scores, tmask, zmask, lengths);

    for (int k = 0; k < NM; k += NB) {
        int rem = NM - k - NB;
        int nR = (rem + 255) / 256;          // row blocks == col blocks
        int gx = nR * 2; if (gx == 0) gx = 1;
        panel64<<<dim3(gx, NMAT), 256>>>(k, nR);
        if (rem > 0) {
            schur64<<<dim3(rem / 64, (rem + 127) / 128, NMAT), 256>>>(k);
        }
    }
    finalize<<<1, 1>>>((float*)d_out);
}

// round 6
// speedup vs baseline: 1.5582x; 1.1235x over previous
#include <cuda_runtime.h>
#include <math.h>
#include <stdint.h>

#define NF 2177      // full node count
#define NM 2176      // minor size (NM = NF-1) = 34*64
#define NMAT 8       // 4 batches x {z, target}
#define NB 64        // panel width
#define NSTEPS (NM/NB)   // 34
#define ROWTILES 17      // 17 * 128 = 2176

// scratch (allocation-free contract: __device__ globals)
__device__ float g_A[NMAT][(size_t)NM * NM];          // ~151.5 MB
__device__ float g_inv[NMAT][NB * NB];                // per-step diag inverse
__device__ float g_part[NMAT][ROWTILES][NM];          // colsum partials
__device__ float g_logparts[NMAT][NSTEPS];            // per-step log det(A11)

// ---------------------------------------------------------------------------
// Build off-diagonal: A[i][j] = -w(r=i+1, c=j+1)
// ---------------------------------------------------------------------------
__global__ void build_offdiag(const float* __restrict__ scores,
                              const float* __restrict__ tmask,
                              const float* __restrict__ zmask,
                              const int* __restrict__ lengths) {
    size_t idx = (size_t)blockIdx.x * blockDim.x + threadIdx.x;
    const size_t total = (size_t)NMAT * NM * NM;
    if (idx >= total) return;
    int j = (int)(idx % NM);
    size_t t = idx / NM;
    int i = (int)(t % NM);
    int m = (int)(t / NM);
    int b = m >> 1;
    const float* mask = (m & 1) ? tmask : zmask;
    int len = lengths[b];
    int r = i + 1, c = j + 1;
    float w = 0.0f;
    if (r < len && c < len) {
        size_t off = (size_t)b * NF * NF + (size_t)r * NF + c;
        float mk = mask[off];
        if (mk != 0.0f) w = expf(scores[off]) * mk;
    }
    g_A[m][(size_t)i * NM + j] = -w;
}

// ---------------------------------------------------------------------------
// Column sums (deterministic two-stage, no atomics)
// ---------------------------------------------------------------------------
__global__ void colsum_part() {
    int m = blockIdx.z;
    int j = blockIdx.x * 32 + threadIdx.x;
    int i0 = blockIdx.y * 128;
    const float* A = g_A[m];
    float s = 0.0f;
    int ibase = i0 + threadIdx.y * 16;
    #pragma unroll
    for (int rr = 0; rr < 16; rr++) {
        s += A[(size_t)(ibase + rr) * NM + j];
    }
    __shared__ float sh[8][32];
    sh[threadIdx.y][threadIdx.x] = s;
    __syncthreads();
    if (threadIdx.y == 0) {
        float tot = 0.0f;
        #pragma unroll
        for (int y = 0; y < 8; y++) tot += sh[y][threadIdx.x];
        g_part[m][blockIdx.y][j] = tot;
    }
}

__global__ void set_diag(const float* __restrict__ scores,
                         const float* __restrict__ tmask,
                         const float* __restrict__ zmask,
                         const int* __restrict__ lengths) {
    int m = blockIdx.y;
    int j = blockIdx.x * 256 + threadIdx.x;
    if (j >= NM) return;
    float s = 0.0f;
    #pragma unroll
    for (int t = 0; t < ROWTILES; t++) s += g_part[m][t][j];
    float colsum = -s;   // partials summed -w
    int b = m >> 1;
    int len = lengths[b];
    int c = j + 1;
    const float* mask = (m & 1) ? tmask : zmask;
    float diag;
    if (c < len) {
        size_t off = (size_t)b * NF * NF + c;   // row 0 (root) entry
        float w0 = expf(scores[off]) * mask[off];
        diag = colsum + w0;
    } else {
        diag = 1.0f;    // pad identity for invalid suffix
    }
    g_A[m][(size_t)j * NM + j] = diag;
}

// ---------------------------------------------------------------------------
// Gauss-Jordan inversion of the 64x64 diagonal block (no pivoting; valid for
// the column-diagonally-dominant M-matrix minors). Cooperative: 4 thr/row.
// Also records log det(A11) for this step. One block per matrix.
// ---------------------------------------------------------------------------
__global__ void __launch_bounds__(256) invdiag(int k) {
    const int m = blockIdx.x;
    float* A = g_A[m];
    const int tid = threadIdx.x;

    __shared__ float M[NB][NB + 1];
    __shared__ float fv[NB];
    __shared__ float lacc;

    for (int e = tid; e < NB * NB; e += 256)
        M[e >> 6][e & 63] = A[(size_t)(k + (e >> 6)) * NM + k + (e & 63)];
    if (tid == 0) lacc = 0.0f;
    __syncthreads();

    const int t  = tid >> 2;          // row owned in phase b
    const int c0 = (tid & 3) * 16;    // col chunk

    for (int p = 0; p < NB; p++) {
        float piv = M[p][p];
        float ipiv = 1.0f / piv;
        if (tid < NB) fv[tid] = M[tid][p];
        __syncthreads();
        // scale row p; thread 0 sets pivot slot and logdet
        if (tid < NB && tid != p) M[p][tid] *= ipiv;
        if (tid == 0) { lacc += logf(piv); M[p][p] = ipiv; }
        __syncthreads();
        // eliminate all other rows
        if (t != p) {
            float f = fv[t];
            #pragma unroll
            for (int qq = 0; qq < 16; qq++) {
                int q = c0 + qq;
                if (q != p) M[t][q] -= f * M[p][q];
            }
            if (p >= c0 && p < c0 + 16) M[t][p] = -f * M[p][p];
        }
        __syncthreads();
    }

    if (tid == 0) g_logparts[m][k / NB] = lacc;
    for (int e = tid; e < NB * NB; e += 256)
        g_inv[m][e] = M[e >> 6][e & 63];
}

// ---------------------------------------------------------------------------
// W = A21 * inv(A11), written in place over A21.  128x64 tile per block,
// 256 threads, 8x4 per thread, K = 64 staged as 2x32.
// ---------------------------------------------------------------------------
__global__ void __launch_bounds__(256) wgemm(int k) {
    const int m = blockIdx.y;
    float* A = g_A[m];
    const float* inv = g_inv[m];
    const int tid = threadIdx.x;
    const int row0 = k + NB + blockIdx.x * 128;

    __shared__ float shA[32][132];   // shA[q][i] = A21[row0+i][kh+q]
    __shared__ float shB[32][68];    // shB[p][j] = inv[kh+p][j]

    const int tx = tid & 15, ty = tid >> 4;
    float acc[8][4] = {};

    #pragma unroll
    for (int h = 0; h < 2; h++) {
        const int kh = k + h * 32;
        __syncthreads();
        {   // A21 slab 128x32 transposed
            int q = tid & 31, y = tid >> 5;
            #pragma unroll
            for (int rr = 0; rr < 16; rr++) {
                int i = rr * 8 + y;
                int rw = row0 + i;
                shA[q][i] = (rw < NM) ? A[(size_t)rw * NM + kh + q] : 0.0f;
            }
        }
        {   // inverse slab 32x64
            int j = tid & 63, pb = tid >> 6;
            #pragma unroll
            for (int rr = 0; rr < 8; rr++) {
                int p = pb + rr * 4;
                shB[p][j] = inv[(h * 32 + p) * NB + j];
            }
        }
        __syncthreads();

        #pragma unroll 8
        for (int p = 0; p < 32; p++) {
            float4 a0 = *(const float4*)&shA[p][ty * 8];
            float4 a1 = *(const float4*)&shA[p][ty * 8 + 4];
            float4 bv = *(const float4*)&shB[p][tx * 4];
            float aa[8] = {a0.x,a0.y,a0.z,a0.w,a1.x,a1.y,a1.z,a1.w};
            float bb[4] = {bv.x,bv.y,bv.z,bv.w};
            #pragma unroll
            for (int ii = 0; ii < 8; ii++)
                #pragma unroll
                for (int jj = 0; jj < 4; jj++)
                    acc[ii][jj] += aa[ii] * bb[jj];
        }
    }

    const int cb = k + tx * 4;
    #pragma unroll
    for (int ii = 0; ii < 8; ii++) {
        int rw = row0 + ty * 8 + ii;
        if (rw >= NM) break;
        *(float4*)(A + (size_t)rw * NM + cb) =
            make_float4(acc[ii][0], acc[ii][1], acc[ii][2], acc[ii][3]);
    }
}

// ---------------------------------------------------------------------------
// Schur update: C[k+64.., k+64..] -= W * A12   (K = 64, staged as 4x16)
// 128x128 tile / block, 256 threads, 8x8 per thread
// ---------------------------------------------------------------------------
__global__ void __launch_bounds__(256) schur128(int k) {
    const int m = blockIdx.z;
    float* A = g_A[m];
    const int base = k + NB;
    const int tid = threadIdx.x;
    const int row0 = base + blockIdx.y * 128;
    const int col0 = base + blockIdx.x * 128;

    __shared__ float shA[16][136];   // shA[p][i] = W[row0+i][k+kh+p]
    __shared__ float shB[16][136];   // shB[p][j] = A12[k+kh+p][col0+j]

    const int tx = tid & 15, ty = tid >> 4;
    float acc[8][8] = {};

    #pragma unroll
    for (int h = 0; h < 4; h++) {
        const int kh = k + h * 16;
        __syncthreads();
        {   // W slab 128x16 transposed
            int q = tid & 15, y = tid >> 4;   // 16 rows per pass
            #pragma unroll
            for (int rr = 0; rr < 8; rr++) {
                int i = rr * 16 + y;
                int rw = row0 + i;
                shA[q][i] = (rw < NM) ? A[(size_t)rw * NM + kh + q] : 0.0f;
            }
        }
        {   // A12 slab 16x128
            int j = tid & 127, pb = tid >> 7;  // 2 rows per pass
            #pragma unroll
            for (int rr = 0; rr < 8; rr++) {
                int p = rr * 2 + pb;
                int cc = col0 + j;
                shB[p][j] = (cc < NM) ? A[(size_t)(kh + p) * NM + cc] : 0.0f;
            }
        }
        __syncthreads();

        #pragma unroll
        for (int p = 0; p < 16; p++) {
            float4 a0 = *(const float4*)&shA[p][ty * 8];
            float4 a1 = *(const float4*)&shA[p][ty * 8 + 4];
            float4 b0 = *(const float4*)&shB[p][tx * 8];
            float4 b1 = *(const float4*)&shB[p][tx * 8 + 4];
            float aa[8] = {a0.x,a0.y,a0.z,a0.w,a1.x,a1.y,a1.z,a1.w};
            float bb[8] = {b0.x,b0.y,b0.z,b0.w,b1.x,b1.y,b1.z,b1.w};
            #pragma unroll
            for (int ii = 0; ii < 8; ii++)
                #pragma unroll
                for (int jj = 0; jj < 8; jj++)
                    acc[ii][jj] += aa[ii] * bb[jj];
        }
    }

    const int cb = col0 + tx * 8;
    #pragma unroll
    for (int ii = 0; ii < 8; ii++) {
        int rw = row0 + ty * 8 + ii;
        if (rw >= NM) break;
        float* cp = A + (size_t)rw * NM + cb;
        if (cb + 7 < NM) {
            float4 v0 = *(float4*)cp;
            float4 v1 = *(float4*)(cp + 4);
            v0.x -= acc[ii][0]; v0.y -= acc[ii][1];
            v0.z -= acc[ii][2]; v0.w -= acc[ii][3];
            v1.x -= acc[ii][4]; v1.y -= acc[ii][5];
            v1.z -= acc[ii][6]; v1.w -= acc[ii][7];
            *(float4*)cp = v0;
            *(float4*)(cp + 4) = v1;
        } else {
            #pragma unroll
            for (int jj = 0; jj < 8; jj++)
                if (cb + jj < NM) cp[jj] -= acc[ii][jj];
        }
    }
}

// ---------------------------------------------------------------------------
// Finalize: mean over batch of (logdet_z - logdet_t), double accumulation
// ---------------------------------------------------------------------------
__global__ void finalize(float* out) {
    double acc = 0.0;
    for (int b = 0; b < 4; b++) {
        double z = 0.0, t = 0.0;
        for (int s = 0; s < NSTEPS; s++) {
            z += (double)g_logparts[2 * b][s];
            t += (double)g_logparts[2 * b + 1][s];
        }
        acc += (z - t);
    }
    out[0] = (float)(acc * 0.25);
}

// ---------------------------------------------------------------------------
extern "C" void kernel_launch(void* const* d_in, const int* in_sizes, int n_in,
                              void* d_out, int out_size) {
    const float* scores  = (const float*)d_in[0];
    const float* tmask   = (const float*)d_in[1];
    const float* zmask   = (const float*)d_in[2];
    const int*   lengths = (const int*)d_in[3];

    const size_t total = (size_t)NMAT * NM * NM;
    build_offdiag<<<(unsigned)((total + 255) / 256), 256>>>(scores, tmask, zmask, lengths);
    colsum_part<<<dim3(NM / 32, ROWTILES, NMAT), dim3(32, 8)>>>();
    set_diag<<<dim3((NM + 255) / 256, NMAT), 256>>>(scores, tmask, zmask, lengths);

    for (int k = 0; k < NM; k += NB) {
        int rem = NM - k - NB;
        invdiag<<<NMAT, 256>>>(k);
        if (rem > 0) {
            wgemm<<<dim3((rem + 127) / 128, NMAT), 256>>>(k);
            int tiles = (rem + 127) / 128;
            schur128<<<dim3(tiles, tiles, NMAT), 256>>>(k);
        }
    }
    finalize<<<1, 1>>>((float*)d_out);
}